// round 14
// baseline (speedup 1.0000x reference)
#include <cuda_runtime.h>
#include <cuda_fp16.h>

#define BATCH   2048
#define TSTEPS  128
#define SLEN    256
#define HID     64
#define EMB     32
#define VOCAB   29
#define GATES   256          // 4*HID
#define ROWH2   36           // enc row stride in half2 units (144 B; bank-conflict-free)

typedef unsigned long long u64;

// f32x2 packed-FMA helpers (sm_100+ PTX; ptxas never emits FFMA2 from C++)
__device__ __forceinline__ u64 pk2(float x, float y) {
    u64 r; asm("mov.b64 %0, {%1, %2};" : "=l"(r) : "f"(x), "f"(y)); return r;
}
__device__ __forceinline__ float2 up2(u64 v) {
    float2 r; asm("mov.b64 {%0, %1}, %2;" : "=f"(r.x), "=f"(r.y) : "l"(v)); return r;
}
__device__ __forceinline__ void fma2(u64& d, u64 a, u64 b) {
    asm("fma.rn.f32x2 %0, %1, %2, %0;" : "+l"(d) : "l"(a), "l"(b));
}

// Precomputed tables (device globals — allocation-free scratch)
__device__ float   g_vocabW[VOCAB * GATES];   // emb@W_ih[:, :32]^T + b_ih + b_hh  (fp32)
__device__ __half2 g_WTh[64 * GATES];         // g_WTh[k2*256+j] = (WT[2k2][j], WT[2k2+1][j]) fp16
__device__ float   g_fcT[128 * 32];           // fcT[d][v] = fc_W[v][d] (v<29 else 0); d: [h(64), ctx(64)]

struct __align__(16) Smem {
    __half2 ench[SLEN * ROWH2];  // 36864 B  enc fp16 pairs, padded rows
    u64     pp[SLEN];            //  2048 B  (p,p) packed pairs
    float   cp[8][2][HID];       //  4096 B  context partials [warp][s-parity][h]
    float   h[2][HID];           //   512 B  double-buffered hidden state
    float   ctx[HID];            //   256 B
    float   fp[8][32];           //  1024 B  fc partials
    float   wsum[8];             //    32 B
    int     ybuf[TSTEPS];        //   512 B
};  // ~45.3 KB -> 2 CTAs/SM

__global__ void setup_vocabW(const float* __restrict__ emb,
                             const float* __restrict__ W_ih,
                             const float* __restrict__ b_ih,
                             const float* __restrict__ b_hh) {
    int v = blockIdx.x, j = threadIdx.x;
    float acc = b_ih[j] + b_hh[j];
#pragma unroll
    for (int e = 0; e < EMB; e++)
        acc += emb[v * EMB + e] * W_ih[j * (EMB + HID) + e];
    g_vocabW[v * GATES + j] = acc;
}

__device__ __forceinline__ float wt_elem(const float* W_ih, const float* W_hh, int k, int j) {
    // x = [ctx(64), h(64)]
    return (k < HID) ? W_ih[j * (EMB + HID) + EMB + k] : W_hh[j * HID + (k - HID)];
}

__global__ void setup_WTh(const float* __restrict__ W_ih,
                          const float* __restrict__ W_hh) {
    int k2 = blockIdx.x, j = threadIdx.x;   // k2 in [0,64)
    float w0 = wt_elem(W_ih, W_hh, 2 * k2 + 0, j);
    float w1 = wt_elem(W_ih, W_hh, 2 * k2 + 1, j);
    g_WTh[k2 * GATES + j] = __floats2half2_rn(w0, w1);
}

__global__ void setup_fcT(const float* __restrict__ fc_W) {
    int d = blockIdx.x, v = threadIdx.x;   // grid 128, block 32
    g_fcT[d * 32 + v] = (v < VOCAB) ? fc_W[v * 2 * HID + d] : 0.0f;
}

__device__ __forceinline__ float fsigmoid(float x) {
    return __fdividef(1.0f, 1.0f + __expf(-fmaxf(x, -80.0f)));
}
__device__ __forceinline__ float ftanh(float x) {
    float e = __expf(fminf(2.0f * x, 80.0f));
    return 1.0f - __fdividef(2.0f, e + 1.0f);
}

__global__ __launch_bounds__(256, 2)
void decoder_kernel(const int* __restrict__ y,
                    const float* __restrict__ h0,
                    const float* __restrict__ c0,
                    const float* __restrict__ enc,
                    const float* __restrict__ fc_b,
                    float* __restrict__ out) {
    extern __shared__ char smem_raw[];
    Smem& S = *reinterpret_cast<Smem*>(smem_raw);

    const int tid  = threadIdx.x;
    const int lane = tid & 31;
    const int wid  = tid >> 5;
    const int b    = blockIdx.x;

    // Gate ownership: 4 adjacent lanes hold the 4 gates (i,f,g,o) of hidden dim j.
    const int q    = tid & 3;          // 0:i 1:f 2:g 3:o
    const int j    = tid >> 2;         // hidden dim [0,64)
    const int gidx = q * 64 + j;       // row in canonical 256-gate order

    // ---- Gate weights in registers: full 128-weight column as 64 half2 ----
    __half2 W2[64];
#pragma unroll
    for (int i = 0; i < 64; i++)
        W2[i] = g_WTh[i * GATES + gidx];

    // ---- Prologue: enc -> fp16 shared (padded rows), coalesced float4 loads ----
    {
        const float4* esrc = reinterpret_cast<const float4*>(enc) + (size_t)b * (SLEN * HID / 4);
#pragma unroll
        for (int it = 0; it < 16; it++) {
            int idx = tid + it * 256;              // 4096 float4s
            int s = idx >> 4, qq = idx & 15;       // qq: 4-float chunk within row
            float4 v = esrc[idx];
            __half2* dst = &S.ench[s * ROWH2 + 2 * qq];
            dst[0] = __floats2half2_rn(v.x, v.y);
            dst[1] = __floats2half2_rn(v.z, v.w);
        }
    }
    float c_reg = (q == 0) ? c0[b * HID + j] : 0.0f;
    if (tid < HID) S.h[0][tid] = h0[b * HID + tid];
    if (tid < TSTEPS) S.ybuf[tid] = y[b * TSTEPS + tid];
    __syncthreads();

    // ---- Score row (s = tid) cached in registers for the whole kernel: 32 regs ----
    uint4 erg[8];
    {
        const uint4* erow4 = reinterpret_cast<const uint4*>(&S.ench[tid * ROWH2]);
#pragma unroll
        for (int k = 0; k < 8; k++) erg[k] = erow4[k];
    }

    const ulonglong2* ctx2 = reinterpret_cast<const ulonglong2*>(S.ctx);
    float* outp = out + (size_t)b * TSTEPS * VOCAB + tid;   // strength-reduced out ptr

    // ---- Timestep loop ----
    for (int t = 0; t < TSTEPS; t++) {
        const int oldb = t & 1, newb = oldb ^ 1;
        const ulonglong2* hOld2 = reinterpret_cast<const ulonglong2*>(S.h[oldb]);
        const int v = S.ybuf[t];                    // early LDS, consumed in Phase D

        // Phase A: score[s=tid] = encReg . h ; p = exp(score); (p,p) packed + warp sums.
        // Zero smem traffic for enc — only the 16 h broadcasts.
        {
            u64 a0 = 0ull, a1 = 0ull;
#pragma unroll
            for (int k = 0; k < 8; k++) {
                uint4 ev = erg[k];                         // register-resident row
                ulonglong2 hh0 = hOld2[2 * k];             // 4 fp32 h (broadcast)
                ulonglong2 hh1 = hOld2[2 * k + 1];
                float2 e0 = __half22float2(*reinterpret_cast<__half2*>(&ev.x));
                float2 e1 = __half22float2(*reinterpret_cast<__half2*>(&ev.y));
                float2 e2 = __half22float2(*reinterpret_cast<__half2*>(&ev.z));
                float2 e3 = __half22float2(*reinterpret_cast<__half2*>(&ev.w));
                fma2(a0, pk2(e0.x, e0.y), hh0.x);
                fma2(a0, pk2(e1.x, e1.y), hh0.y);
                fma2(a1, pk2(e2.x, e2.y), hh1.x);
                fma2(a1, pk2(e3.x, e3.y), hh1.y);
            }
            float2 f0 = up2(a0), f1 = up2(a1);
            float p = __expf((f0.x + f0.y) + (f1.x + f1.y));
            S.pp[tid] = pk2(p, p);
            float ws = p;
#pragma unroll
            for (int o = 16; o; o >>= 1) ws += __shfl_xor_sync(~0u, ws, o);
            if (lane == 0) S.wsum[wid] = ws;
        }
        __syncwarp();   // pp[s] produced and consumed within the same warp

        // Phase B: context partials. Warp w covers s in [32w,32w+32).
        // lanes 0-15 -> even s, 16-31 -> odd s; lane handles 4 h values (LDS.64).
        {
            const int hi = lane >> 4, lo = lane & 15;
            const __half2* ebase = &S.ench[(wid * 32 + hi) * ROWH2 + lo * 2];
            const u64* ppb = &S.pp[wid * 32 + hi];
            u64 a0 = 0ull, a1 = 0ull;
#pragma unroll
            for (int i = 0; i < 16; i++) {
                u64 ppv = ppb[2 * i];                      // broadcast LDS.64
                uint2 e = *reinterpret_cast<const uint2*>(ebase + (size_t)i * 2 * ROWH2);
                float2 f0 = __half22float2(*reinterpret_cast<__half2*>(&e.x));
                float2 f1 = __half22float2(*reinterpret_cast<__half2*>(&e.y));
                fma2(a0, pk2(f0.x, f0.y), ppv);
                fma2(a1, pk2(f1.x, f1.y), ppv);
            }
            float2 r0 = up2(a0), r1 = up2(a1);
            *reinterpret_cast<float4*>(&S.cp[wid][hi][lo * 4]) =
                make_float4(r0.x, r0.y, r1.x, r1.y);
        }
        __syncthreads();   // (1)

        // Phase D-h (pre-barrier): h-half of the gate dot — depends only on hOld,
        // runs concurrently with Phase C's ctx reduction on warps 0-1.
        float hsum;
        {
            u64 a2 = 0ull, a3 = 0ull;
#pragma unroll
            for (int i = 0; i < 16; i++) {
                ulonglong2 x = hOld2[i];
                float2 wa = __half22float2(W2[32 + 2 * i]);
                float2 wb = __half22float2(W2[33 + 2 * i]);
                fma2(a2, x.x, pk2(wa.x, wa.y));
                fma2(a3, x.y, pk2(wb.x, wb.y));
            }
            float2 s2 = up2(a2), s3 = up2(a3);
            hsum = (s2.x + s2.y) + (s3.x + s3.y);
        }

        // Phase C: reduce partials + normalize -> ctx (threads 0-63)
        if (tid < HID) {
            float z = S.wsum[0];
#pragma unroll
            for (int i = 1; i < 8; i++) z += S.wsum[i];
            float a = 0.f;
#pragma unroll
            for (int w = 0; w < 8; w++) a += S.cp[w][0][tid] + S.cp[w][1][tid];
            S.ctx[tid] = a * __fdividef(1.0f, z);
        }
        __syncthreads();   // (2)

        // Phase D-ctx + E: ctx-half of gate dot, combine, activate; in-warp shuffle
        // gathers i/f/g/o of dim j; q==0 lanes update c (register) and h[newb].
        {
            u64 a0 = 0ull, a1 = 0ull;
#pragma unroll
            for (int i = 0; i < 16; i++) {
                ulonglong2 x = ctx2[i];
                float2 wa = __half22float2(W2[2 * i]);
                float2 wb = __half22float2(W2[2 * i + 1]);
                fma2(a0, x.x, pk2(wa.x, wa.y));
                fma2(a1, x.y, pk2(wb.x, wb.y));
            }
            float2 s0 = up2(a0), s1 = up2(a1);
            float gate = ((s0.x + s0.y) + (s1.x + s1.y)) + hsum
                       + __ldg(&g_vocabW[v * GATES + gidx]);
            float a = (q == 2) ? ftanh(gate) : fsigmoid(gate);

            int lb = lane & ~3;
            float ai = __shfl_sync(~0u, a, lb + 0);
            float af = __shfl_sync(~0u, a, lb + 1);
            float ag = __shfl_sync(~0u, a, lb + 2);
            float ao = __shfl_sync(~0u, a, lb + 3);
            if (q == 0) {
                c_reg = af * c_reg + ai * ag;
                S.h[newb][j] = ao * ftanh(c_reg);
            }
        }
        __syncthreads();   // (3)

        // Phase F: logits partials. Warp w covers d in [16w,16w+16); lane = vocab slot.
        {
            const float4* sF4 = (wid < 4) ? reinterpret_cast<const float4*>(S.h[newb])
                                          : reinterpret_cast<const float4*>(S.ctx);
            int qq = (wid & 3) * 4;
            float4 s0 = sF4[qq], s1 = sF4[qq + 1], s2 = sF4[qq + 2], s3 = sF4[qq + 3];
            const float* fc = &g_fcT[(wid * 16) * 32 + lane];
            float acc;
            acc  = s0.x * __ldg(fc +  0 * 32);
            acc += s0.y * __ldg(fc +  1 * 32);
            acc += s0.z * __ldg(fc +  2 * 32);
            acc += s0.w * __ldg(fc +  3 * 32);
            acc += s1.x * __ldg(fc +  4 * 32);
            acc += s1.y * __ldg(fc +  5 * 32);
            acc += s1.z * __ldg(fc +  6 * 32);
            acc += s1.w * __ldg(fc +  7 * 32);
            acc += s2.x * __ldg(fc +  8 * 32);
            acc += s2.y * __ldg(fc +  9 * 32);
            acc += s2.z * __ldg(fc + 10 * 32);
            acc += s2.w * __ldg(fc + 11 * 32);
            acc += s3.x * __ldg(fc + 12 * 32);
            acc += s3.y * __ldg(fc + 13 * 32);
            acc += s3.z * __ldg(fc + 14 * 32);
            acc += s3.w * __ldg(fc + 15 * 32);
            S.fp[wid][lane] = acc;
        }
        __syncthreads();   // (4)

        if (tid < VOCAB) {
            float acc = __ldg(&fc_b[tid]);
#pragma unroll
            for (int w = 0; w < 8; w++) acc += S.fp[w][tid];
            *outp = acc;
        }
        outp += VOCAB;
        // No trailing barrier: S.fp is next written after 3 barriers of t+1;
        // all other cross-phase hazards audited against barriers (1)-(4).
    }
}

extern "C" void kernel_launch(void* const* d_in, const int* in_sizes, int n_in,
                              void* d_out, int out_size) {
    const int*   y     = (const int*)  d_in[0];
    const float* h0    = (const float*)d_in[1];
    const float* c0    = (const float*)d_in[2];
    const float* enc   = (const float*)d_in[3];
    const float* emb   = (const float*)d_in[4];
    const float* W_ih  = (const float*)d_in[5];
    const float* W_hh  = (const float*)d_in[6];
    const float* b_ih  = (const float*)d_in[7];
    const float* b_hh  = (const float*)d_in[8];
    const float* fc_W  = (const float*)d_in[9];
    const float* fc_b  = (const float*)d_in[10];
    float* out = (float*)d_out;
    (void)in_sizes; (void)n_in; (void)out_size;

    setup_vocabW<<<VOCAB, GATES>>>(emb, W_ih, b_ih, b_hh);
    setup_WTh<<<64, GATES>>>(W_ih, W_hh);
    setup_fcT<<<128, 32>>>(fc_W);

    cudaFuncSetAttribute(decoder_kernel,
                         cudaFuncAttributeMaxDynamicSharedMemorySize,
                         (int)sizeof(Smem));
    decoder_kernel<<<BATCH, 256, sizeof(Smem)>>>(y, h0, c0, enc, fc_b, out);
}

// round 15
// speedup vs baseline: 1.3372x; 1.3372x over previous
#include <cuda_runtime.h>
#include <cuda_fp16.h>

#define BATCH   2048
#define TSTEPS  128
#define SLEN    256
#define HID     64
#define EMB     32
#define VOCAB   29
#define GATES   256          // 4*HID
#define ROWH2   36           // enc row stride in half2 units (144 B; bank-conflict-free)

typedef unsigned long long u64;

// f32x2 packed-FMA helpers (sm_100+ PTX; ptxas never emits FFMA2 from C++)
__device__ __forceinline__ u64 pk2(float x, float y) {
    u64 r; asm("mov.b64 %0, {%1, %2};" : "=l"(r) : "f"(x), "f"(y)); return r;
}
__device__ __forceinline__ float2 up2(u64 v) {
    float2 r; asm("mov.b64 {%0, %1}, %2;" : "=f"(r.x), "=f"(r.y) : "l"(v)); return r;
}
__device__ __forceinline__ void fma2(u64& d, u64 a, u64 b) {
    asm("fma.rn.f32x2 %0, %1, %2, %0;" : "+l"(d) : "l"(a), "l"(b));
}

// Precomputed tables (device globals — allocation-free scratch)
__device__ float   g_vocabW[VOCAB * GATES];   // emb@W_ih[:, :32]^T + b_ih + b_hh  (fp32)
__device__ __half2 g_WTh[64 * GATES];         // g_WTh[k2*256+j] = (WT[2k2][j], WT[2k2+1][j]) fp16
__device__ float   g_fcT[128 * 32];           // fcT[d][v] = fc_W[v][d] (v<29 else 0); d: [h(64), ctx(64)]

struct __align__(16) Smem {
    __half2 ench[SLEN * ROWH2];  // 36864 B  enc fp16 pairs, padded rows
    float   pf[SLEN];            //  1024 B  unnormalized softmax weights (plain float)
    float   cp[8][HID];          //  2048 B  context partials per warp
    float   h[2][HID];           //   512 B  double-buffered hidden state
    float   ctx[HID];            //   256 B
    float   fp[8][32];           //  1024 B  fc partials
    float   wsum[8];             //    32 B
    int     ybuf[TSTEPS];        //   512 B
};  // ~42.2 KB -> 2 CTAs/SM

__global__ void setup_vocabW(const float* __restrict__ emb,
                             const float* __restrict__ W_ih,
                             const float* __restrict__ b_ih,
                             const float* __restrict__ b_hh) {
    int v = blockIdx.x, j = threadIdx.x;
    float acc = b_ih[j] + b_hh[j];
#pragma unroll
    for (int e = 0; e < EMB; e++)
        acc += emb[v * EMB + e] * W_ih[j * (EMB + HID) + e];
    g_vocabW[v * GATES + j] = acc;
}

__device__ __forceinline__ float wt_elem(const float* W_ih, const float* W_hh, int k, int j) {
    // x = [ctx(64), h(64)]
    return (k < HID) ? W_ih[j * (EMB + HID) + EMB + k] : W_hh[j * HID + (k - HID)];
}

__global__ void setup_WTh(const float* __restrict__ W_ih,
                          const float* __restrict__ W_hh) {
    int k2 = blockIdx.x, j = threadIdx.x;   // k2 in [0,64)
    float w0 = wt_elem(W_ih, W_hh, 2 * k2 + 0, j);
    float w1 = wt_elem(W_ih, W_hh, 2 * k2 + 1, j);
    g_WTh[k2 * GATES + j] = __floats2half2_rn(w0, w1);
}

__global__ void setup_fcT(const float* __restrict__ fc_W) {
    int d = blockIdx.x, v = threadIdx.x;   // grid 128, block 32
    g_fcT[d * 32 + v] = (v < VOCAB) ? fc_W[v * 2 * HID + d] : 0.0f;
}

__device__ __forceinline__ float fsigmoid(float x) {
    return __fdividef(1.0f, 1.0f + __expf(-fmaxf(x, -80.0f)));
}
__device__ __forceinline__ float ftanh(float x) {
    float e = __expf(fminf(2.0f * x, 80.0f));
    return 1.0f - __fdividef(2.0f, e + 1.0f);
}

__global__ __launch_bounds__(256, 2)
void decoder_kernel(const int* __restrict__ y,
                    const float* __restrict__ h0,
                    const float* __restrict__ c0,
                    const float* __restrict__ enc,
                    const float* __restrict__ fc_b,
                    float* __restrict__ out) {
    extern __shared__ char smem_raw[];
    Smem& S = *reinterpret_cast<Smem*>(smem_raw);

    const int tid  = threadIdx.x;
    const int lane = tid & 31;
    const int wid  = tid >> 5;
    const int b    = blockIdx.x;

    // Gate ownership: 4 adjacent lanes hold the 4 gates (i,f,g,o) of hidden dim j.
    const int q    = tid & 3;          // 0:i 1:f 2:g 3:o
    const int j    = tid >> 2;         // hidden dim [0,64)
    const int gidx = q * 64 + j;       // row in canonical 256-gate order

    // ---- Gate weights in registers: full 128-weight column as 64 half2 ----
    __half2 W2[64];
#pragma unroll
    for (int i = 0; i < 64; i++)
        W2[i] = g_WTh[i * GATES + gidx];

    // ---- Prologue: enc -> fp16 shared (padded rows), coalesced float4 loads ----
    {
        const float4* esrc = reinterpret_cast<const float4*>(enc) + (size_t)b * (SLEN * HID / 4);
#pragma unroll
        for (int it = 0; it < 16; it++) {
            int idx = tid + it * 256;              // 4096 float4s
            int s = idx >> 4, qq = idx & 15;       // qq: 4-float chunk within row
            float4 v = esrc[idx];
            __half2* dst = &S.ench[s * ROWH2 + 2 * qq];
            dst[0] = __floats2half2_rn(v.x, v.y);
            dst[1] = __floats2half2_rn(v.z, v.w);
        }
    }
    float c_reg = (q == 0) ? c0[b * HID + j] : 0.0f;
    if (tid < HID) S.h[0][tid] = h0[b * HID + tid];
    if (tid < TSTEPS) S.ybuf[tid] = y[b * TSTEPS + tid];
    __syncthreads();

    // ---- Phase-B column cache: lane l of warp w holds enc[32w+i, 2l:2l+2] (32 regs) ----
    __half2 eclm[32];
#pragma unroll
    for (int i = 0; i < 32; i++)
        eclm[i] = S.ench[(wid * 32 + i) * ROWH2 + lane];

    const uint4*      erow4 = reinterpret_cast<const uint4*>(&S.ench[tid * ROWH2]);
    const ulonglong2* ctx2  = reinterpret_cast<const ulonglong2*>(S.ctx);
    float* outp = out + (size_t)b * TSTEPS * VOCAB + tid;   // strength-reduced out ptr

    // ---- Timestep loop ----
    for (int t = 0; t < TSTEPS; t++) {
        const int oldb = t & 1, newb = oldb ^ 1;
        const ulonglong2* hOld2 = reinterpret_cast<const ulonglong2*>(S.h[oldb]);
        const int v = S.ybuf[t];                    // early LDS, consumed in Phase D

        // Phase A: score[s=tid] = enc16[s,:].h (smem rows) ; p = exp(score); warp sums.
        {
            u64 a0 = 0ull, a1 = 0ull;
#pragma unroll
            for (int k = 0; k < 8; k++) {
                uint4 ev = erow4[k];                       // own row from smem
                ulonglong2 hh0 = hOld2[2 * k];             // 4 fp32 h (broadcast)
                ulonglong2 hh1 = hOld2[2 * k + 1];
                float2 e0 = __half22float2(*reinterpret_cast<__half2*>(&ev.x));
                float2 e1 = __half22float2(*reinterpret_cast<__half2*>(&ev.y));
                float2 e2 = __half22float2(*reinterpret_cast<__half2*>(&ev.z));
                float2 e3 = __half22float2(*reinterpret_cast<__half2*>(&ev.w));
                fma2(a0, pk2(e0.x, e0.y), hh0.x);
                fma2(a0, pk2(e1.x, e1.y), hh0.y);
                fma2(a1, pk2(e2.x, e2.y), hh1.x);
                fma2(a1, pk2(e3.x, e3.y), hh1.y);
            }
            float2 f0 = up2(a0), f1 = up2(a1);
            float p = __expf((f0.x + f0.y) + (f1.x + f1.y));
            S.pf[tid] = p;
            float ws = p;
#pragma unroll
            for (int o = 16; o; o >>= 1) ws += __shfl_xor_sync(~0u, ws, o);
            if (lane == 0) S.wsum[wid] = ws;
        }
        __syncwarp();   // pf[32w..32w+32) produced and consumed within the same warp

        // Phase B: context partials from REGISTER columns — only p broadcasts hit smem.
        // Lane l accumulates ctx h-pair (2l, 2l+1) over warp's 32 s values.
        {
            const float* pfb = &S.pf[wid * 32];
            u64 a0 = 0ull, a1 = 0ull;
#pragma unroll
            for (int i = 0; i < 16; i++) {
                float2 pv = *reinterpret_cast<const float2*>(&pfb[2 * i]);  // broadcast
                float2 e0 = __half22float2(eclm[2 * i]);
                float2 e1 = __half22float2(eclm[2 * i + 1]);
                fma2(a0, pk2(e0.x, e0.y), pk2(pv.x, pv.x));
                fma2(a1, pk2(e1.x, e1.y), pk2(pv.y, pv.y));
            }
            float2 r0 = up2(a0), r1 = up2(a1);
            *reinterpret_cast<float2*>(&S.cp[wid][2 * lane]) =
                make_float2(r0.x + r1.x, r0.y + r1.y);
        }
        __syncthreads();   // (1)

        // Phase D-h (pre-barrier): h-half of the gate dot — depends only on hOld,
        // runs concurrently with Phase C's ctx reduction on warps 0-1.
        float hsum;
        {
            u64 a2 = 0ull, a3 = 0ull;
#pragma unroll
            for (int i = 0; i < 16; i++) {
                ulonglong2 x = hOld2[i];
                float2 wa = __half22float2(W2[32 + 2 * i]);
                float2 wb = __half22float2(W2[33 + 2 * i]);
                fma2(a2, x.x, pk2(wa.x, wa.y));
                fma2(a3, x.y, pk2(wb.x, wb.y));
            }
            float2 s2 = up2(a2), s3 = up2(a3);
            hsum = (s2.x + s2.y) + (s3.x + s3.y);
        }

        // Phase C: reduce partials + normalize -> ctx (threads 0-63)
        if (tid < HID) {
            float z = S.wsum[0];
#pragma unroll
            for (int i = 1; i < 8; i++) z += S.wsum[i];
            float a = 0.f;
#pragma unroll
            for (int w = 0; w < 8; w++) a += S.cp[w][tid];
            S.ctx[tid] = a * __fdividef(1.0f, z);
        }
        __syncthreads();   // (2)

        // Phase D-ctx + E: ctx-half of gate dot, combine, activate; in-warp shuffle
        // gathers i/f/g/o of dim j; q==0 lanes update c (register) and h[newb].
        {
            u64 a0 = 0ull, a1 = 0ull;
#pragma unroll
            for (int i = 0; i < 16; i++) {
                ulonglong2 x = ctx2[i];
                float2 wa = __half22float2(W2[2 * i]);
                float2 wb = __half22float2(W2[2 * i + 1]);
                fma2(a0, x.x, pk2(wa.x, wa.y));
                fma2(a1, x.y, pk2(wb.x, wb.y));
            }
            float2 s0 = up2(a0), s1 = up2(a1);
            float gate = ((s0.x + s0.y) + (s1.x + s1.y)) + hsum
                       + __ldg(&g_vocabW[v * GATES + gidx]);
            float a = (q == 2) ? ftanh(gate) : fsigmoid(gate);

            int lb = lane & ~3;
            float ai = __shfl_sync(~0u, a, lb + 0);
            float af = __shfl_sync(~0u, a, lb + 1);
            float ag = __shfl_sync(~0u, a, lb + 2);
            float ao = __shfl_sync(~0u, a, lb + 3);
            if (q == 0) {
                c_reg = af * c_reg + ai * ag;
                S.h[newb][j] = ao * ftanh(c_reg);
            }
        }
        __syncthreads();   // (3)

        // Phase F: logits partials. Warp w covers d in [16w,16w+16); lane = vocab slot.
        {
            const float4* sF4 = (wid < 4) ? reinterpret_cast<const float4*>(S.h[newb])
                                          : reinterpret_cast<const float4*>(S.ctx);
            int qq = (wid & 3) * 4;
            float4 s0 = sF4[qq], s1 = sF4[qq + 1], s2 = sF4[qq + 2], s3 = sF4[qq + 3];
            const float* fc = &g_fcT[(wid * 16) * 32 + lane];
            float acc;
            acc  = s0.x * __ldg(fc +  0 * 32);
            acc += s0.y * __ldg(fc +  1 * 32);
            acc += s0.z * __ldg(fc +  2 * 32);
            acc += s0.w * __ldg(fc +  3 * 32);
            acc += s1.x * __ldg(fc +  4 * 32);
            acc += s1.y * __ldg(fc +  5 * 32);
            acc += s1.z * __ldg(fc +  6 * 32);
            acc += s1.w * __ldg(fc +  7 * 32);
            acc += s2.x * __ldg(fc +  8 * 32);
            acc += s2.y * __ldg(fc +  9 * 32);
            acc += s2.z * __ldg(fc + 10 * 32);
            acc += s2.w * __ldg(fc + 11 * 32);
            acc += s3.x * __ldg(fc + 12 * 32);
            acc += s3.y * __ldg(fc + 13 * 32);
            acc += s3.z * __ldg(fc + 14 * 32);
            acc += s3.w * __ldg(fc + 15 * 32);
            S.fp[wid][lane] = acc;
        }
        __syncthreads();   // (4)

        if (tid < VOCAB) {
            float acc = __ldg(&fc_b[tid]);
#pragma unroll
            for (int w = 0; w < 8; w++) acc += S.fp[w][tid];
            *outp = acc;
        }
        outp += VOCAB;
        // No trailing barrier: S.fp is next written after 3 barriers of t+1;
        // all other cross-phase hazards audited against barriers (1)-(4).
    }
}

extern "C" void kernel_launch(void* const* d_in, const int* in_sizes, int n_in,
                              void* d_out, int out_size) {
    const int*   y     = (const int*)  d_in[0];
    const float* h0    = (const float*)d_in[1];
    const float* c0    = (const float*)d_in[2];
    const float* enc   = (const float*)d_in[3];
    const float* emb   = (const float*)d_in[4];
    const float* W_ih  = (const float*)d_in[5];
    const float* W_hh  = (const float*)d_in[6];
    const float* b_ih  = (const float*)d_in[7];
    const float* b_hh  = (const float*)d_in[8];
    const float* fc_W  = (const float*)d_in[9];
    const float* fc_b  = (const float*)d_in[10];
    float* out = (float*)d_out;
    (void)in_sizes; (void)n_in; (void)out_size;

    setup_vocabW<<<VOCAB, GATES>>>(emb, W_ih, b_ih, b_hh);
    setup_WTh<<<64, GATES>>>(W_ih, W_hh);
    setup_fcT<<<128, 32>>>(fc_W);

    cudaFuncSetAttribute(decoder_kernel,
                         cudaFuncAttributeMaxDynamicSharedMemorySize,
                         (int)sizeof(Smem));
    decoder_kernel<<<BATCH, 256, sizeof(Smem)>>>(y, h0, c0, enc, fc_b, out);
}